// round 5
// baseline (speedup 1.0000x reference)
#include <cuda_runtime.h>
#include <cuda_bf16.h>
#include <cstdint>

// Problem shape (fixed for this bench)
#define Bdim 128
#define Tdim 784
#define Kdim 512   // K of branch GEMMs
#define Hdim 512   // N of branch GEMMs
#define Odim 10
#define Mdim (Bdim * Tdim)   // 100352

// ---------------------------------------------------------------------------
// Scratch (device globals: allocation inside kernel_launch is forbidden)
// ---------------------------------------------------------------------------
__device__ float g_d1[(size_t)Mdim * Hdim];
__device__ float g_d2[(size_t)Mdim * Hdim];
__device__ float g_spk[(size_t)Mdim * Hdim];

// ---------------------------------------------------------------------------
// Helpers
// ---------------------------------------------------------------------------
__device__ __forceinline__ uint32_t smem_u32(const void* p) {
    uint32_t a;
    asm("{ .reg .u64 t; cvta.to.shared.u64 t, %1; cvt.u32.u64 %0, t; }"
        : "=r"(a) : "l"(p));
    return a;
}

// Packed fp32x2 FMA: d.lo = fma(a.lo,b.lo,d.lo), d.hi = fma(a.hi,b.hi,d.hi)
// Each half is an IEEE fp32 RN FMA -> bit-exact vs scalar FFMA chains.
#define FFMA2(d, a, b) \
    asm volatile("fma.rn.f32x2 %0, %1, %2, %0;" : "+l"(d) : "l"(a), "l"(b))

#define LDS_V2U64(r0, r1, addr) \
    asm volatile("ld.shared.v2.u64 {%0, %1}, [%2];" \
                 : "=l"(r0), "=l"(r1) : "r"(addr))

#define STS_U64(addr, v) \
    asm volatile("st.shared.b64 [%0], %1;" :: "r"(addr), "l"(v) : "memory")

#define PACK2(out, lo, hi) \
    asm("mov.b64 %0, {%1, %2};" : "=l"(out) : "f"(lo), "f"(hi))

#define UNPACK2(lo, hi, in) \
    asm("mov.b64 {%0, %1}, %2;" : "=f"(lo), "=f"(hi) : "l"(in))

// ---------------------------------------------------------------------------
// GEMM kernel: D[branch] = X @ W[branch]^T + b[branch]
//   Bit-exact fp32 (sequential-k FFMA rounding per output), but 2 outputs per
//   instruction via packed fma.rn.f32x2.
//   grid: (8, 784). x: branch = x>>2, n0 = (x&3)*128. y: m0 = y*128.
//   CTA 128x128, K in 32 chunks of BK=16, double-buffered SMEM.
//   Xs holds X DUPLICATED: Xs[k][2m] = Xs[k][2m+1] = X[m][k]  (broadcast side)
//   Ws holds W transposed:  Ws[k][n] = W[n][k]                (pair side)
// ---------------------------------------------------------------------------
#define BK 16
#define LDX 260                       // floats per Xs k-row (256 data + 4 pad), 16B-mult
#define LDW 132                       // floats per Ws k-row (128 data + 4 pad), 16B-mult
#define XBUF (BK * LDX)               // floats per X buffer
#define WBUF (BK * LDW)
#define SMEM_BYTES ((2 * XBUF + 2 * WBUF) * 4)   // 50176 B

__global__ void __launch_bounds__(256, 2) gemm_f32x2_kernel(
    const float* __restrict__ X,
    const float* __restrict__ W1, const float* __restrict__ b1,
    const float* __restrict__ W2, const float* __restrict__ b2)
{
    extern __shared__ float sm[];
    float* Xs = sm;                   // [2][BK][LDX]
    float* Ws = sm + 2 * XBUF;        // [2][BK][LDW]
    const uint32_t xs_u = smem_u32(Xs);
    const uint32_t ws_u = smem_u32(Ws);

    const int tid = threadIdx.x;
    const int tx = tid & 15;          // n direction (8 cols each)
    const int ty = tid >> 4;          // m direction (8 rows each)

    const int branch = blockIdx.x >> 2;
    const int n0 = (blockIdx.x & 3) * 128;
    const int m0 = blockIdx.y * 128;

    const float* __restrict__ W    = branch ? W2 : W1;
    const float* __restrict__ bias = branch ? b2 : b1;
    float*       __restrict__ D    = branch ? g_d2 : g_d1;

    // Loader mapping: row = tid>>1 (0..127), k-half = (tid&1)*8
    const int lrow = tid >> 1;
    const int lkb  = (tid & 1) * 8;
    const float* xg = X + (size_t)(m0 + lrow) * Kdim + lkb;
    const float* wg = W + (size_t)(n0 + lrow) * Kdim + lkb;

    uint64_t acc[8][4];
    #pragma unroll
    for (int i = 0; i < 8; i++)
        #pragma unroll
        for (int j = 0; j < 4; j++) acc[i][j] = 0ull;

    float4 xr0, xr1, wr0, wr1;        // prefetch registers (one chunk)

#define LDG_CHUNK(c) do {                                                   \
        const float* _x = xg + (c) * BK;                                    \
        const float* _w = wg + (c) * BK;                                    \
        xr0 = *(const float4*)_x;  xr1 = *(const float4*)(_x + 4);          \
        wr0 = *(const float4*)_w;  wr1 = *(const float4*)(_w + 4);          \
    } while (0)

    // Store prefetched regs into buffer p (X duplicated, W transposed)
#define STS_CHUNK(p) do {                                                   \
        const float _xv[8] = {xr0.x, xr0.y, xr0.z, xr0.w,                   \
                              xr1.x, xr1.y, xr1.z, xr1.w};                  \
        const float _wv[8] = {wr0.x, wr0.y, wr0.z, wr0.w,                   \
                              wr1.x, wr1.y, wr1.z, wr1.w};                  \
        const uint32_t _xb = xs_u + ((p) * XBUF + lkb * LDX + 2 * lrow) * 4;\
        const uint32_t _wb = ws_u + ((p) * WBUF + lkb * LDW + lrow) * 4;    \
        _Pragma("unroll")                                                   \
        for (int _j = 0; _j < 8; _j++) {                                    \
            uint64_t _d; PACK2(_d, _xv[_j], _xv[_j]);                       \
            STS_U64(_xb + _j * (LDX * 4), _d);                              \
            Ws[(p) * WBUF + (lkb + _j) * LDW + lrow] = _wv[_j];             \
        }                                                                   \
    } while (0)

    LDG_CHUNK(0);
    STS_CHUNK(0);

    for (int c = 0; c < 32; ++c) {
        const int p = c & 1;
        __syncthreads();
        if (c < 31) LDG_CHUNK(c + 1);

        const uint32_t xa = xs_u + (p * XBUF + ty * 16) * 4;   // 2m base = ty*16
        const uint32_t wa = ws_u + (p * WBUF + tx * 8) * 4;

        #pragma unroll
        for (int kk = 0; kk < BK; kk++) {
            uint64_t a2[8], b2[4];
            LDS_V2U64(a2[0], a2[1], xa + kk * (LDX * 4));
            LDS_V2U64(a2[2], a2[3], xa + kk * (LDX * 4) + 16);
            LDS_V2U64(a2[4], a2[5], xa + kk * (LDX * 4) + 32);
            LDS_V2U64(a2[6], a2[7], xa + kk * (LDX * 4) + 48);
            LDS_V2U64(b2[0], b2[1], wa + kk * (LDW * 4));
            LDS_V2U64(b2[2], b2[3], wa + kk * (LDW * 4) + 16);
            #pragma unroll
            for (int i = 0; i < 8; i++)
                #pragma unroll
                for (int j = 0; j < 4; j++)
                    FFMA2(acc[i][j], a2[i], b2[j]);
        }

        if (c < 31) STS_CHUNK(p ^ 1);
    }

    // Epilogue: unpack pairs, add bias, store 2x float4 per row
    {
        const int nb = n0 + tx * 8;
        float bsv[8];
        #pragma unroll
        for (int j = 0; j < 8; j++) bsv[j] = bias[nb + j];

        #pragma unroll
        for (int i = 0; i < 8; i++) {
            const int m = m0 + ty * 8 + i;
            float v[8];
            #pragma unroll
            for (int j = 0; j < 4; j++)
                UNPACK2(v[2 * j], v[2 * j + 1], acc[i][j]);
            float4 o0 = make_float4(v[0] + bsv[0], v[1] + bsv[1],
                                    v[2] + bsv[2], v[3] + bsv[3]);
            float4 o1 = make_float4(v[4] + bsv[4], v[5] + bsv[5],
                                    v[6] + bsv[6], v[7] + bsv[7]);
            float* dst = D + (size_t)m * Hdim + nb;
            *(float4*)dst = o0;
            *(float4*)(dst + 4) = o1;
        }
    }
}

// ---------------------------------------------------------------------------
// Kernel B: sequential LIF scan over T. One thread per (b,h).
// ---------------------------------------------------------------------------
__device__ __forceinline__ float sigmoidf(float x) { return 1.f / (1.f + expf(-x)); }

__global__ void __launch_bounds__(256) scan_kernel(
    const float* __restrict__ tau_m,
    const float* __restrict__ tau_n1,
    const float* __restrict__ tau_n2,
    const float* __restrict__ mem0,
    const float* __restrict__ spike0)
{
    const int tid = blockIdx.x * blockDim.x + threadIdx.x;
    const int b = tid / Hdim;
    const int h = tid - b * Hdim;

    const float alpha = sigmoidf(tau_m[h]);
    const float beta1 = sigmoidf(tau_n1[h]);
    const float beta2 = sigmoidf(tau_n2[h]);
    const float om_a = 1.f - alpha, om_b1 = 1.f - beta1, om_b2 = 1.f - beta2;

    float mem = mem0[tid];
    float spk = spike0[tid];
    float d1 = 0.f, d2 = 0.f;

    size_t base = ((size_t)b * Tdim) * Hdim + h;
    const float* __restrict__ D1 = g_d1;
    const float* __restrict__ D2 = g_d2;
    float* __restrict__ S = g_spk;

    #pragma unroll 4
    for (int t = 0; t < Tdim; t++) {
        float d1t = D1[base];
        float d2t = D2[base];
        d1 = beta1 * d1 + om_b1 * d1t;
        d2 = beta2 * d2 + om_b2 * d2t;
        mem = mem * alpha + om_a * (d1 + d2) - spk;   // V_TH = 1
        spk = (mem > 1.f) ? 1.f : 0.f;
        S[base] = spk;
        base += Hdim;
    }
}

// ---------------------------------------------------------------------------
// Kernel C: readout  out[m, o] = sum_h S[m,h] * Wr[o,h] + br[o]
// ---------------------------------------------------------------------------
__global__ void __launch_bounds__(256) readout_kernel(
    const float* __restrict__ Wr,
    const float* __restrict__ br,
    float* __restrict__ Out)
{
    __shared__ float WrS[Odim * Hdim];
    __shared__ float brS[Odim];
    for (int i = threadIdx.x; i < Odim * Hdim; i += blockDim.x) WrS[i] = Wr[i];
    if (threadIdx.x < Odim) brS[threadIdx.x] = br[threadIdx.x];
    __syncthreads();

    const int warp = threadIdx.x >> 5;
    const int lane = threadIdx.x & 31;
    const int m = blockIdx.x * 8 + warp;
    const float* __restrict__ row = g_spk + (size_t)m * Hdim;

    float acc[Odim];
    #pragma unroll
    for (int o = 0; o < Odim; o++) acc[o] = 0.f;

    for (int hh = lane; hh < Hdim; hh += 32) {
        float s = row[hh];
        #pragma unroll
        for (int o = 0; o < Odim; o++)
            acc[o] = fmaf(s, WrS[o * Hdim + hh], acc[o]);
    }

    #pragma unroll
    for (int o = 0; o < Odim; o++)
        #pragma unroll
        for (int d = 16; d; d >>= 1)
            acc[o] += __shfl_xor_sync(0xffffffffu, acc[o], d);

    if (lane == 0) {
        #pragma unroll
        for (int o = 0; o < Odim; o++)
            Out[(size_t)m * Odim + o] = acc[o] + brS[o];
    }
}

// ---------------------------------------------------------------------------
// Launch
// ---------------------------------------------------------------------------
extern "C" void kernel_launch(void* const* d_in, const int* in_sizes, int n_in,
                              void* d_out, int out_size)
{
    const float* input_data = (const float*)d_in[0];
    const float* W1     = (const float*)d_in[1];
    const float* b1     = (const float*)d_in[2];
    const float* W2     = (const float*)d_in[3];
    const float* b2     = (const float*)d_in[4];
    const float* tau_m  = (const float*)d_in[5];
    const float* tau_n1 = (const float*)d_in[6];
    const float* tau_n2 = (const float*)d_in[7];
    const float* Wr     = (const float*)d_in[8];
    const float* br     = (const float*)d_in[9];
    const float* mem0   = (const float*)d_in[10];
    const float* spike0 = (const float*)d_in[11];
    float* out = (float*)d_out;

    (void)in_sizes; (void)n_in; (void)out_size;

    cudaFuncSetAttribute(gemm_f32x2_kernel,
                         cudaFuncAttributeMaxDynamicSharedMemorySize, SMEM_BYTES);

    dim3 ggrid(8, Mdim / 128);   // (branch*4 + n-tile, m-tile)
    gemm_f32x2_kernel<<<ggrid, 256, SMEM_BYTES>>>(input_data, W1, b1, W2, b2);

    scan_kernel<<<(Bdim * Hdim) / 256, 256>>>(tau_m, tau_n1, tau_n2, mem0, spike0);

    readout_kernel<<<Mdim / 8, 256>>>(Wr, br, out);
}

// round 6
// speedup vs baseline: 1.1670x; 1.1670x over previous
#include <cuda_runtime.h>
#include <cuda_bf16.h>
#include <cstdint>

// Problem shape (fixed for this bench)
#define Bdim 128
#define Tdim 784
#define Kdim 512   // K of branch GEMMs
#define Hdim 512   // N of branch GEMMs
#define Odim 10
#define Mdim (Bdim * Tdim)   // 100352

// ---------------------------------------------------------------------------
// Scratch (device globals: allocation inside kernel_launch is forbidden)
// ---------------------------------------------------------------------------
__device__ float g_d1[(size_t)Mdim * Hdim];
__device__ float g_d2[(size_t)Mdim * Hdim];
__device__ float g_spk[(size_t)Mdim * Hdim];

// ---------------------------------------------------------------------------
// Helpers
// ---------------------------------------------------------------------------
__device__ __forceinline__ uint32_t smem_u32(const void* p) {
    uint32_t a;
    asm("{ .reg .u64 t; cvta.to.shared.u64 t, %1; cvt.u32.u64 %0, t; }"
        : "=r"(a) : "l"(p));
    return a;
}

// Packed fp32x2 FMA: d.lo = fma(a.lo,b.lo,d.lo), d.hi = fma(a.hi,b.hi,d.hi)
// Each lane is an IEEE fp32 RN FMA -> bit-exact vs scalar FFMA chains.
#define FFMA2(d, a, b) \
    asm volatile("fma.rn.f32x2 %0, %1, %2, %0;" : "+l"(d) : "l"(a), "l"(b))

#define LDS_V2U64(r0, r1, addr) \
    asm volatile("ld.shared.v2.u64 {%0, %1}, [%2];" \
                 : "=l"(r0), "=l"(r1) : "r"(addr))

#define PACK2(out, lo, hi) \
    asm("mov.b64 %0, {%1, %2};" : "=l"(out) : "f"(lo), "f"(hi))

#define UNPACK2(lo, hi, in) \
    asm("mov.b64 {%0, %1}, %2;" : "=f"(lo), "=f"(hi) : "l"(in))

// ---------------------------------------------------------------------------
// GEMM kernel: D[branch] = X @ W[branch]^T + b[branch]
//   Bit-exact fp32 (ascending-k IEEE FMA chain per output) via fma.rn.f32x2.
//   Accumulator pairs along M: A pairs load naturally from SMEM (no dup);
//   B scalars duplicated in registers (1 mov each).
//   grid: (8, 784). x: branch = x>>2, n0 = (x&3)*128. y: m0 = y*128.
//   CTA 128x128, K in 32 chunks of BK=16, double-buffered SMEM.
//   Xs[k][m] = X[m][k], Ws[k][n] = W[n][k]  (both transposed, no duplication)
// ---------------------------------------------------------------------------
#define BK 16
#define LDX 132                       // floats per k-row (128 data + 4 pad)
#define XBUF (BK * LDX)               // floats per buffer (per matrix)
#define SMEM_BYTES (4 * XBUF * 4)     // X[2] + W[2] = 33792 B

__global__ void __launch_bounds__(256, 2) gemm_f32x2_kernel(
    const float* __restrict__ X,
    const float* __restrict__ W1, const float* __restrict__ b1,
    const float* __restrict__ W2, const float* __restrict__ b2)
{
    extern __shared__ float sm[];
    float* Xs = sm;                   // [2][BK][LDX]
    float* Ws = sm + 2 * XBUF;        // [2][BK][LDX]
    const uint32_t xs_u = smem_u32(Xs);

    const int tid = threadIdx.x;
    const int tx = tid & 15;          // n direction (8 cols each)
    const int ty = tid >> 4;          // m direction (8 rows each)

    const int branch = blockIdx.x >> 2;
    const int n0 = (blockIdx.x & 3) * 128;
    const int m0 = blockIdx.y * 128;

    const float* __restrict__ W    = branch ? W2 : W1;
    const float* __restrict__ bias = branch ? b2 : b1;
    float*       __restrict__ D    = branch ? g_d2 : g_d1;

    // Loader mapping: row = tid>>1 (0..127), k-half = (tid&1)*8
    const int lrow = tid >> 1;
    const int lkb  = (tid & 1) * 8;
    const float* xg = X + (size_t)(m0 + lrow) * Kdim + lkb;
    const float* wg = W + (size_t)(n0 + lrow) * Kdim + lkb;

    // acc[i][j]: m-pair i (rows ty*8+2i, ty*8+2i+1), col j (n0+tx*8+j)
    uint64_t acc[4][8];
    #pragma unroll
    for (int i = 0; i < 4; i++)
        #pragma unroll
        for (int j = 0; j < 8; j++) acc[i][j] = 0ull;

    float4 xr0, xr1, wr0, wr1;        // prefetch registers (one chunk)

#define LDG_CHUNK(c) do {                                                   \
        const float* _x = xg + (c) * BK;                                    \
        const float* _w = wg + (c) * BK;                                    \
        xr0 = *(const float4*)_x;  xr1 = *(const float4*)(_x + 4);          \
        wr0 = *(const float4*)_w;  wr1 = *(const float4*)(_w + 4);          \
    } while (0)

    // Store prefetched regs into buffer p (both matrices transposed, scalar)
#define STS_CHUNK(p) do {                                                   \
        const float _xv[8] = {xr0.x, xr0.y, xr0.z, xr0.w,                   \
                              xr1.x, xr1.y, xr1.z, xr1.w};                  \
        const float _wv[8] = {wr0.x, wr0.y, wr0.z, wr0.w,                   \
                              wr1.x, wr1.y, wr1.z, wr1.w};                  \
        _Pragma("unroll")                                                   \
        for (int _j = 0; _j < 8; _j++) {                                    \
            Xs[(p) * XBUF + (lkb + _j) * LDX + lrow] = _xv[_j];             \
            Ws[(p) * XBUF + (lkb + _j) * LDX + lrow] = _wv[_j];             \
        }                                                                   \
    } while (0)

    LDG_CHUNK(0);
    STS_CHUNK(0);

    for (int c = 0; c < 32; ++c) {
        const int p = c & 1;
        __syncthreads();
        if (c < 31) LDG_CHUNK(c + 1);

        const uint32_t xa = xs_u + (p * XBUF + ty * 8) * 4;
        const float*   wrow = Ws + p * XBUF + tx * 8;

        #pragma unroll
        for (int kk = 0; kk < BK; kk++) {
            // A: 8 m-values as 4 natural pairs
            uint64_t a[4];
            LDS_V2U64(a[0], a[1], xa + kk * (LDX * 4));
            LDS_V2U64(a[2], a[3], xa + kk * (LDX * 4) + 16);
            // B: 8 n-values, duplicated into pairs in registers
            const float4 w0 = *(const float4*)(wrow + kk * LDX);
            const float4 w1 = *(const float4*)(wrow + kk * LDX + 4);
            uint64_t bd[8];
            PACK2(bd[0], w0.x, w0.x); PACK2(bd[1], w0.y, w0.y);
            PACK2(bd[2], w0.z, w0.z); PACK2(bd[3], w0.w, w0.w);
            PACK2(bd[4], w1.x, w1.x); PACK2(bd[5], w1.y, w1.y);
            PACK2(bd[6], w1.z, w1.z); PACK2(bd[7], w1.w, w1.w);
            #pragma unroll
            for (int i = 0; i < 4; i++)
                #pragma unroll
                for (int j = 0; j < 8; j++)
                    FFMA2(acc[i][j], a[i], bd[j]);
        }

        if (c < 31) STS_CHUNK(p ^ 1);
    }

    // Epilogue: unpack pairs, add bias, store 2 rows x 8 floats per m-pair
    {
        const int nb = n0 + tx * 8;
        float bsv[8];
        #pragma unroll
        for (int j = 0; j < 8; j++) bsv[j] = bias[nb + j];

        #pragma unroll
        for (int i = 0; i < 4; i++) {
            const int m = m0 + ty * 8 + 2 * i;
            float ve[8], vo[8];
            #pragma unroll
            for (int j = 0; j < 8; j++)
                UNPACK2(ve[j], vo[j], acc[i][j]);
            float* de = D + (size_t)m * Hdim + nb;
            float* dodd = de + Hdim;
            *(float4*)de = make_float4(ve[0] + bsv[0], ve[1] + bsv[1],
                                       ve[2] + bsv[2], ve[3] + bsv[3]);
            *(float4*)(de + 4) = make_float4(ve[4] + bsv[4], ve[5] + bsv[5],
                                             ve[6] + bsv[6], ve[7] + bsv[7]);
            *(float4*)dodd = make_float4(vo[0] + bsv[0], vo[1] + bsv[1],
                                         vo[2] + bsv[2], vo[3] + bsv[3]);
            *(float4*)(dodd + 4) = make_float4(vo[4] + bsv[4], vo[5] + bsv[5],
                                               vo[6] + bsv[6], vo[7] + bsv[7]);
        }
    }
}

// ---------------------------------------------------------------------------
// Kernel B: sequential LIF scan over T. One thread per (b,h).
// ---------------------------------------------------------------------------
__device__ __forceinline__ float sigmoidf(float x) { return 1.f / (1.f + expf(-x)); }

__global__ void __launch_bounds__(256) scan_kernel(
    const float* __restrict__ tau_m,
    const float* __restrict__ tau_n1,
    const float* __restrict__ tau_n2,
    const float* __restrict__ mem0,
    const float* __restrict__ spike0)
{
    const int tid = blockIdx.x * blockDim.x + threadIdx.x;
    const int b = tid / Hdim;
    const int h = tid - b * Hdim;

    const float alpha = sigmoidf(tau_m[h]);
    const float beta1 = sigmoidf(tau_n1[h]);
    const float beta2 = sigmoidf(tau_n2[h]);
    const float om_a = 1.f - alpha, om_b1 = 1.f - beta1, om_b2 = 1.f - beta2;

    float mem = mem0[tid];
    float spk = spike0[tid];
    float d1 = 0.f, d2 = 0.f;

    size_t base = ((size_t)b * Tdim) * Hdim + h;
    const float* __restrict__ D1 = g_d1;
    const float* __restrict__ D2 = g_d2;
    float* __restrict__ S = g_spk;

    #pragma unroll 4
    for (int t = 0; t < Tdim; t++) {
        float d1t = D1[base];
        float d2t = D2[base];
        d1 = beta1 * d1 + om_b1 * d1t;
        d2 = beta2 * d2 + om_b2 * d2t;
        mem = mem * alpha + om_a * (d1 + d2) - spk;   // V_TH = 1
        spk = (mem > 1.f) ? 1.f : 0.f;
        S[base] = spk;
        base += Hdim;
    }
}

// ---------------------------------------------------------------------------
// Kernel C: readout  out[m, o] = sum_h S[m,h] * Wr[o,h] + br[o]
// ---------------------------------------------------------------------------
__global__ void __launch_bounds__(256) readout_kernel(
    const float* __restrict__ Wr,
    const float* __restrict__ br,
    float* __restrict__ Out)
{
    __shared__ float WrS[Odim * Hdim];
    __shared__ float brS[Odim];
    for (int i = threadIdx.x; i < Odim * Hdim; i += blockDim.x) WrS[i] = Wr[i];
    if (threadIdx.x < Odim) brS[threadIdx.x] = br[threadIdx.x];
    __syncthreads();

    const int warp = threadIdx.x >> 5;
    const int lane = threadIdx.x & 31;
    const int m = blockIdx.x * 8 + warp;
    const float* __restrict__ row = g_spk + (size_t)m * Hdim;

    float acc[Odim];
    #pragma unroll
    for (int o = 0; o < Odim; o++) acc[o] = 0.f;

    for (int hh = lane; hh < Hdim; hh += 32) {
        float s = row[hh];
        #pragma unroll
        for (int o = 0; o < Odim; o++)
            acc[o] = fmaf(s, WrS[o * Hdim + hh], acc[o]);
    }

    #pragma unroll
    for (int o = 0; o < Odim; o++)
        #pragma unroll
        for (int d = 16; d; d >>= 1)
            acc[o] += __shfl_xor_sync(0xffffffffu, acc[o], d);

    if (lane == 0) {
        #pragma unroll
        for (int o = 0; o < Odim; o++)
            Out[(size_t)m * Odim + o] = acc[o] + brS[o];
    }
}

// ---------------------------------------------------------------------------
// Launch
// ---------------------------------------------------------------------------
extern "C" void kernel_launch(void* const* d_in, const int* in_sizes, int n_in,
                              void* d_out, int out_size)
{
    const float* input_data = (const float*)d_in[0];
    const float* W1     = (const float*)d_in[1];
    const float* b1     = (const float*)d_in[2];
    const float* W2     = (const float*)d_in[3];
    const float* b2     = (const float*)d_in[4];
    const float* tau_m  = (const float*)d_in[5];
    const float* tau_n1 = (const float*)d_in[6];
    const float* tau_n2 = (const float*)d_in[7];
    const float* Wr     = (const float*)d_in[8];
    const float* br     = (const float*)d_in[9];
    const float* mem0   = (const float*)d_in[10];
    const float* spike0 = (const float*)d_in[11];
    float* out = (float*)d_out;

    (void)in_sizes; (void)n_in; (void)out_size;

    cudaFuncSetAttribute(gemm_f32x2_kernel,
                         cudaFuncAttributeMaxDynamicSharedMemorySize, SMEM_BYTES);

    dim3 ggrid(8, Mdim / 128);   // (branch*4 + n-tile, m-tile)
    gemm_f32x2_kernel<<<ggrid, 256, SMEM_BYTES>>>(input_data, W1, b1, W2, b2);

    scan_kernel<<<(Bdim * Hdim) / 256, 256>>>(tau_m, tau_n1, tau_n2, mem0, spike0);

    readout_kernel<<<Mdim / 8, 256>>>(Wr, br, out);
}

// round 7
// speedup vs baseline: 1.2647x; 1.0837x over previous
#include <cuda_runtime.h>
#include <cuda_bf16.h>
#include <cstdint>

// Problem shape (fixed for this bench)
#define Bdim 128
#define Tdim 784
#define Kdim 512   // K of branch GEMMs
#define Hdim 512   // N of branch GEMMs
#define Odim 10
#define Mdim (Bdim * Tdim)   // 100352

// ---------------------------------------------------------------------------
// Scratch (device globals: allocation inside kernel_launch is forbidden)
// ---------------------------------------------------------------------------
__device__ float    g_d1[(size_t)Mdim * Hdim];
__device__ float    g_d2[(size_t)Mdim * Hdim];
__device__ uint32_t g_ballot[(size_t)Mdim * 16];   // 512 spikes -> 16 words per (b,t)

// ---------------------------------------------------------------------------
// GEMM kernel: D[branch] = X @ W[branch]^T + b[branch]
//   Bit-exact fp32: each output is an ascending-k chain of scalar IEEE FMAs.
//   grid: (8, 784). x: branch = x>>2, n0 = (x&3)*128. y: m0 = y*128.
//   CTA 128x128, K in 32 chunks of BK=16, double-buffered SMEM,
//   explicit register-fragment double-buffering in the kk loop.
// ---------------------------------------------------------------------------
#define BK 16
#define LDSX 132                      // floats per k-row (128 data + 4 pad)
#define XBUF (BK * LDSX)              // floats per stage per matrix
#define SMEM_BYTES (4 * XBUF * 4)     // X[2] + W[2] = 33792 B

__global__ void __launch_bounds__(256, 2) gemm_kernel(
    const float* __restrict__ X,
    const float* __restrict__ W1, const float* __restrict__ b1,
    const float* __restrict__ W2, const float* __restrict__ b2)
{
    extern __shared__ float sm[];
    float* Xs = sm;                   // [2][BK][LDSX]  Xs[k][m] = X[m][k]
    float* Ws = sm + 2 * XBUF;        // [2][BK][LDSX]  Ws[k][n] = W[n][k]

    const int tid = threadIdx.x;
    const int tx = tid & 15;          // n direction (8 cols each)
    const int ty = tid >> 4;          // m direction (8 rows each)

    const int branch = blockIdx.x >> 2;
    const int n0 = (blockIdx.x & 3) * 128;
    const int m0 = blockIdx.y * 128;

    const float* __restrict__ W    = branch ? W2 : W1;
    const float* __restrict__ bias = branch ? b2 : b1;
    float*       __restrict__ D    = branch ? g_d2 : g_d1;

    // Loader mapping (coalesced): row = tid>>2 (0..63, +64), col = (tid&3)*4
    const int lrow = tid >> 2;
    const int lcol = (tid & 3) * 4;
    const float* xg = X + (size_t)(m0 + lrow) * Kdim + lcol;
    const float* wg = W + (size_t)(n0 + lrow) * Kdim + lcol;

    float acc[8][8];
    #pragma unroll
    for (int i = 0; i < 8; i++)
        #pragma unroll
        for (int j = 0; j < 8; j++) acc[i][j] = 0.f;

    float4 xr[2], wr[2];              // gmem prefetch registers (one chunk)

#define LDG_CHUNK(c) do {                                                   \
        xr[0] = *(const float4*)(xg + (c) * BK);                            \
        xr[1] = *(const float4*)(xg + (size_t)64 * Kdim + (c) * BK);        \
        wr[0] = *(const float4*)(wg + (c) * BK);                            \
        wr[1] = *(const float4*)(wg + (size_t)64 * Kdim + (c) * BK);        \
    } while (0)

#define STS_CHUNK(p) do {                                                   \
        _Pragma("unroll")                                                   \
        for (int _r = 0; _r < 2; _r++) {                                    \
            const float _xv[4] = {xr[_r].x, xr[_r].y, xr[_r].z, xr[_r].w};  \
            const float _wv[4] = {wr[_r].x, wr[_r].y, wr[_r].z, wr[_r].w};  \
            _Pragma("unroll")                                               \
            for (int _u = 0; _u < 4; _u++) {                                \
                Xs[(p) * XBUF + (lcol + _u) * LDSX + lrow + _r * 64] = _xv[_u]; \
                Ws[(p) * XBUF + (lcol + _u) * LDSX + lrow + _r * 64] = _wv[_u]; \
            }                                                               \
        }                                                                   \
    } while (0)

#define LDFRAG(buf, kk) do {                                                \
        const float* _xr = xb + (kk) * LDSX + ty * 8;                       \
        const float* _wr = wb + (kk) * LDSX + tx * 8;                       \
        *(float4*)&fa[buf][0] = *(const float4*)_xr;                        \
        *(float4*)&fa[buf][4] = *(const float4*)(_xr + 4);                  \
        *(float4*)&fb[buf][0] = *(const float4*)_wr;                        \
        *(float4*)&fb[buf][4] = *(const float4*)(_wr + 4);                  \
    } while (0)

    LDG_CHUNK(0);
    STS_CHUNK(0);

    for (int c = 0; c < 32; ++c) {
        const int p = c & 1;
        __syncthreads();
        if (c < 31) LDG_CHUNK(c + 1);

        const float* xb = Xs + p * XBUF;
        const float* wb = Ws + p * XBUF;

        float fa[2][8], fb[2][8];     // fragment double buffer
        LDFRAG(0, 0);
        #pragma unroll
        for (int kk = 0; kk < BK; kk++) {
            const int cur = kk & 1;
            if (kk < BK - 1) LDFRAG(cur ^ 1, kk + 1);
            #pragma unroll
            for (int i = 0; i < 8; i++)
                #pragma unroll
                for (int j = 0; j < 8; j++)
                    acc[i][j] = fmaf(fa[cur][i], fb[cur][j], acc[i][j]);
        }

        if (c < 31) STS_CHUNK(p ^ 1);
    }

    // Epilogue: add bias, store 2x float4 per row
    {
        const int nb = n0 + tx * 8;
        float bsv[8];
        #pragma unroll
        for (int j = 0; j < 8; j++) bsv[j] = bias[nb + j];

        #pragma unroll
        for (int i = 0; i < 8; i++) {
            const int m = m0 + ty * 8 + i;
            float* dst = D + (size_t)m * Hdim + nb;
            *(float4*)dst = make_float4(acc[i][0] + bsv[0], acc[i][1] + bsv[1],
                                        acc[i][2] + bsv[2], acc[i][3] + bsv[3]);
            *(float4*)(dst + 4) = make_float4(acc[i][4] + bsv[4], acc[i][5] + bsv[5],
                                              acc[i][6] + bsv[6], acc[i][7] + bsv[7]);
        }
    }
}

// ---------------------------------------------------------------------------
// Kernel B: sequential LIF scan over T. One thread per (b,h).
// Spikes emitted as warp ballots (32 spikes per uint32) — 6.4 MB total.
// ---------------------------------------------------------------------------
__device__ __forceinline__ float sigmoidf(float x) { return 1.f / (1.f + expf(-x)); }

__global__ void __launch_bounds__(256) scan_kernel(
    const float* __restrict__ tau_m,
    const float* __restrict__ tau_n1,
    const float* __restrict__ tau_n2,
    const float* __restrict__ mem0,
    const float* __restrict__ spike0)
{
    const int tid = blockIdx.x * blockDim.x + threadIdx.x;
    const int b = tid / Hdim;
    const int h = tid - b * Hdim;
    const int lane = threadIdx.x & 31;

    const float alpha = sigmoidf(tau_m[h]);
    const float beta1 = sigmoidf(tau_n1[h]);
    const float beta2 = sigmoidf(tau_n2[h]);
    const float om_a = 1.f - alpha, om_b1 = 1.f - beta1, om_b2 = 1.f - beta2;

    float mem = mem0[tid];
    float spk = spike0[tid];
    float d1 = 0.f, d2 = 0.f;

    size_t base = ((size_t)b * Tdim) * Hdim + h;
    size_t bidx = ((size_t)b * Tdim) * 16 + (h >> 5);   // ballot slot at t=0
    const float* __restrict__ D1 = g_d1;
    const float* __restrict__ D2 = g_d2;

    #pragma unroll 4
    for (int t = 0; t < Tdim; t++) {
        float d1t = __ldcs(D1 + base);
        float d2t = __ldcs(D2 + base);
        d1 = beta1 * d1 + om_b1 * d1t;
        d2 = beta2 * d2 + om_b2 * d2t;
        mem = mem * alpha + om_a * (d1 + d2) - spk;   // V_TH = 1
        spk = (mem > 1.f) ? 1.f : 0.f;
        unsigned bal = __ballot_sync(0xffffffffu, mem > 1.f);
        if (lane == 0) g_ballot[bidx] = bal;
        base += Hdim;
        bidx += 16;
    }
}

// ---------------------------------------------------------------------------
// Kernel C: readout from spike ballots
//   out[m,o] = sum_h bit(m,h) * Wr[o,h] + br[o]
//   One warp per m; per-lane h-order and shuffle tree identical to the
//   previous float-spike version -> bit-identical output.
// ---------------------------------------------------------------------------
__global__ void __launch_bounds__(256) readout_kernel(
    const float* __restrict__ Wr,
    const float* __restrict__ br,
    float* __restrict__ Out)
{
    __shared__ float WrS[Odim * Hdim];   // 20 KB
    __shared__ float brS[Odim];
    for (int i = threadIdx.x; i < Odim * Hdim; i += blockDim.x) WrS[i] = Wr[i];
    if (threadIdx.x < Odim) brS[threadIdx.x] = br[threadIdx.x];
    __syncthreads();

    const int warp = threadIdx.x >> 5;
    const int lane = threadIdx.x & 31;
    const int m = blockIdx.x * 8 + warp;

    // one coalesced 64B read: lanes 0..15 hold the 16 ballot words of row m
    const uint32_t* gb = g_ballot + (size_t)m * 16;
    uint32_t w = (lane < 16) ? gb[lane] : 0u;

    float acc[Odim];
    #pragma unroll
    for (int o = 0; o < Odim; o++) acc[o] = 0.f;

    #pragma unroll
    for (int j = 0; j < 16; j++) {               // h = j*32 + lane (ascending)
        const uint32_t wj = __shfl_sync(0xffffffffu, w, j);
        const float s = ((wj >> lane) & 1u) ? 1.f : 0.f;
        const int hh = j * 32 + lane;
        #pragma unroll
        for (int o = 0; o < Odim; o++)
            acc[o] = fmaf(s, WrS[o * Hdim + hh], acc[o]);
    }

    #pragma unroll
    for (int o = 0; o < Odim; o++)
        #pragma unroll
        for (int d = 16; d; d >>= 1)
            acc[o] += __shfl_xor_sync(0xffffffffu, acc[o], d);

    if (lane == 0) {
        #pragma unroll
        for (int o = 0; o < Odim; o++)
            Out[(size_t)m * Odim + o] = acc[o] + brS[o];
    }
}

// ---------------------------------------------------------------------------
// Launch
// ---------------------------------------------------------------------------
extern "C" void kernel_launch(void* const* d_in, const int* in_sizes, int n_in,
                              void* d_out, int out_size)
{
    const float* input_data = (const float*)d_in[0];
    const float* W1     = (const float*)d_in[1];
    const float* b1     = (const float*)d_in[2];
    const float* W2     = (const float*)d_in[3];
    const float* b2     = (const float*)d_in[4];
    const float* tau_m  = (const float*)d_in[5];
    const float* tau_n1 = (const float*)d_in[6];
    const float* tau_n2 = (const float*)d_in[7];
    const float* Wr     = (const float*)d_in[8];
    const float* br     = (const float*)d_in[9];
    const float* mem0   = (const float*)d_in[10];
    const float* spike0 = (const float*)d_in[11];
    float* out = (float*)d_out;

    (void)in_sizes; (void)n_in; (void)out_size;

    cudaFuncSetAttribute(gemm_kernel,
                         cudaFuncAttributeMaxDynamicSharedMemorySize, SMEM_BYTES);

    dim3 ggrid(8, Mdim / 128);   // (branch*4 + n-tile, m-tile)
    gemm_kernel<<<ggrid, 256, SMEM_BYTES>>>(input_data, W1, b1, W2, b2);

    scan_kernel<<<(Bdim * Hdim) / 256, 256>>>(tau_m, tau_n1, tau_n2, mem0, spike0);

    readout_kernel<<<Mdim / 8, 256>>>(Wr, br, out);
}